// round 12
// baseline (speedup 1.0000x reference)
#include <cuda_runtime.h>
#include <cuda_fp16.h>
#include <cstdint>

#define BATCH   8192
#define DIM     1024
#define HALF_B  4096

// ---------------- device scratch (static, no runtime alloc) ----------------
__device__ __half g_P[2][BATCH][DIM];          // permuted, normalized, fp16 (32 MB)
__device__ int   g_perm[BATCH];
__device__ float g_S[2][2][BATCH];             // [same=0/cross=1][feature][row]

// ---------------- helpers ----------------
__device__ __forceinline__ uint32_t smem_u32(const void* p) {
    uint32_t a;
    asm("{ .reg .u64 t; cvta.to.shared.u64 t, %1; cvt.u32.u64 %0, t; }" : "=r"(a) : "l"(p));
    return a;
}
__device__ __forceinline__ void cpa16(uint32_t s, const void* g) {
    asm volatile("cp.async.cg.shared.global [%0], [%1], 16;" :: "r"(s), "l"(g) : "memory");
}
#define SWZ(o) ((o) ^ (((o) >> 3) & 0x70))

__device__ __forceinline__ void ldmatrix_x4(uint32_t& r0, uint32_t& r1, uint32_t& r2, uint32_t& r3,
                                            uint32_t addr) {
    asm volatile("ldmatrix.sync.aligned.m8n8.x4.shared.b16 {%0,%1,%2,%3}, [%4];"
                 : "=r"(r0), "=r"(r1), "=r"(r2), "=r"(r3) : "r"(addr));
}
// fp16 MMA with fp16 accumulators: D(2 regs) = A(4) * B(2) + D
__device__ __forceinline__ void mma16816h(uint32_t* c, const uint32_t* a, const uint32_t* b) {
    asm volatile("mma.sync.aligned.m16n8k16.row.col.f16.f16.f16.f16 "
                 "{%0,%1}, {%2,%3,%4,%5}, {%6,%7}, {%0,%1};"
                 : "+r"(c[0]), "+r"(c[1])
                 : "r"(a[0]), "r"(a[1]), "r"(a[2]), "r"(a[3]), "r"(b[0]), "r"(b[1]));
}

// ---------------- kernel 1: permutation (stable partition by label) ----------------
__global__ void perm_kernel(const int* __restrict__ label) {
    __shared__ int wsum[32];
    int t = threadIdx.x;
    int l[8]; int c = 0;
#pragma unroll
    for (int i = 0; i < 8; i++) { l[i] = label[t * 8 + i]; c += l[i]; }
    int v = c, lane = t & 31, w = t >> 5;
#pragma unroll
    for (int o = 1; o < 32; o <<= 1) {
        int n = __shfl_up_sync(0xffffffffu, v, o);
        if (lane >= o) v += n;
    }
    if (lane == 31) wsum[w] = v;
    __syncthreads();
    if (w == 0) {
        int x = wsum[lane];
#pragma unroll
        for (int o = 1; o < 32; o <<= 1) {
            int n = __shfl_up_sync(0xffffffffu, x, o);
            if (lane >= o) x += n;
        }
        wsum[lane] = x;
    }
    __syncthreads();
    int run = v - c + (w ? wsum[w - 1] : 0);   // ones strictly before t*8
#pragma unroll
    for (int i = 0; i < 8; i++) {
        int idx = t * 8 + i;
        g_perm[idx] = l[i] ? run : (HALF_B + (idx - run));
        run += l[i];
    }
}

// ---------------- kernel 2: normalize + scatter to fp16 ----------------
__global__ void norm_kernel(const float* __restrict__ text, const float* __restrict__ image) {
    int f = blockIdx.y;
    int row = blockIdx.x;
    int t = threadIdx.x;
    const float4* src = (const float4*)((f == 0 ? text : image) + (size_t)row * DIM);
    float4 v = src[t];
    float s = v.x * v.x + v.y * v.y + v.z * v.z + v.w * v.w;
#pragma unroll
    for (int o = 16; o; o >>= 1) s += __shfl_xor_sync(0xffffffffu, s, o);
    __shared__ float ws[8];
    __shared__ float s_inv;
    if ((t & 31) == 0) ws[t >> 5] = s;
    __syncthreads();
    if (t == 0) {
        float a = 0.f;
#pragma unroll
        for (int wq = 0; wq < 8; wq++) a += ws[wq];
        s_inv = 1.0f / fmaxf(sqrtf(a), 1e-12f);
    }
    __syncthreads();
    float inv = s_inv;
    int dest = g_perm[row];
    __half* dst = &g_P[f][dest][0];
    __half2 a0 = __floats2half2_rn(v.x * inv, v.y * inv);
    __half2 a1 = __floats2half2_rn(v.z * inv, v.w * inv);
    ((__half2*)dst)[2 * t]     = a0;
    ((__half2*)dst)[2 * t + 1] = a1;
}

// ---------------- dummy kernel (aligns ncu capture window onto gram_kernel) --------
__global__ void dummy_kernel() {}

// ---------------- kernel 3: symmetric Gram GEMM (HMMA f16-accum) + exp-sum epilogue
// 128x128 tile per CTA, lower-triangular tile pairs only. 4 warps, warp tile 64x64,
// 2 CTAs/SM. Single barrier per chunk, per-chunk fragment prime, k-step
// double-buffering, XOR-folded addresses, x4 B-fragment loads.
constexpr int NCHUNK = DIM / 64, STAGES = 3;
constexpr int STAGE_A = 128 * 128;          // 16 KB (128 rows x 64 fp16)
constexpr int STAGE_BYTES = 2 * STAGE_A;    // 32 KB (A + B)
constexpr int SMEM_DYN = STAGES * STAGE_BYTES;   // 96 KB
constexpr int NTILE = BATCH / 128;          // 64
constexpr int NPAIR = NTILE * (NTILE + 1) / 2;   // 2080

__global__ void __launch_bounds__(128, 2) gram_kernel() {
    extern __shared__ __align__(1024) char smem_raw[];
    uint32_t sb = smem_u32(smem_raw);
    int tid = threadIdx.x, lane = tid & 31, wid = tid >> 5;
    int p = blockIdx.x, f = blockIdx.y;

    // triangular decode: tm >= tn
    int tm = (int)((sqrtf(8.f * (float)p + 1.f) - 1.f) * 0.5f);
    while ((tm + 1) * (tm + 2) / 2 <= p) tm++;
    while (tm * (tm + 1) / 2 > p) tm--;
    int tn = p - tm * (tm + 1) / 2;
    bool diag = (tm == tn);

    const char* baseA = (const char*)&g_P[f][tm * 128][0];
    const char* baseB = (const char*)&g_P[f][tn * 128][0];

    auto load_chunk = [&](int c, int s) {
        uint32_t dA = sb + s * STAGE_BYTES;
        uint32_t dB = dA + STAGE_A;
        const char* gA = baseA + c * 128;
        const char* gB = baseB + c * 128;
#pragma unroll
        for (int i = 0; i < 8; i++) {       // A: 128 rows x 8 segs = 1024 cp / 128 thr
            int o = tid + (i << 7); int r = o >> 3, sg = o & 7;
            cpa16(dA + SWZ(r * 128 + sg * 16), gA + (size_t)r * 2048 + sg * 16);
        }
#pragma unroll
        for (int i = 0; i < 8; i++) {
            int o = tid + (i << 7); int r = o >> 3, sg = o & 7;
            cpa16(dB + SWZ(r * 128 + sg * 16), gB + (size_t)r * 2048 + sg * 16);
        }
        asm volatile("cp.async.commit_group;" ::: "memory");
    };

    // prologue: 2 chunks in flight
    load_chunk(0, 0);
    load_chunk(1, 1);

    int wm = wid & 1, wn = wid >> 1;
    int rWarp = wm * 64;            // warp's M offset within tile
    int cWarp = wn * 64;            // warp's N offset within tile
    int quad = lane >> 3, laneRow = lane & 7;
    int aRowOff = rWarp + (quad & 1) * 8 + laneRow;   // + mi*16
    int aColOff = (quad >> 1) * 8;                    // + ks*16 cols
    // B via x4: two n8-fragments (rows nb*16..nb*16+15) per op
    int bRow4 = cWarp + ((lane >> 4) & 1) * 8 + laneRow;  // + nb*16
    int bCol4 = ((lane >> 3) & 1) * 8;                    // k half

    // swizzled fragment base offsets (ks=0); addr(ks) = base ^ (32*ks)
    uint32_t aB[4], bB4[4];
#pragma unroll
    for (int mi = 0; mi < 4; mi++)
        aB[mi] = SWZ((uint32_t)((aRowOff + mi * 16) * 128 + aColOff * 2));
#pragma unroll
    for (int nb = 0; nb < 4; nb++)
        bB4[nb] = SWZ((uint32_t)((bRow4 + nb * 16) * 128 + bCol4 * 2));

    // fp16 accumulators: 2 regs per (mi,ni) fragment (half2 x2)
    uint32_t acc[4][8][2];
#pragma unroll
    for (int mi = 0; mi < 4; mi++)
#pragma unroll
        for (int ni = 0; ni < 8; ni++)
            acc[mi][ni][0] = acc[mi][ni][1] = 0u;

    uint32_t af[2][4][4], bf[2][8][2];

    auto prime = [&](int buf, uint32_t dA, uint32_t dB, uint32_t kx) {
#pragma unroll
        for (int mi = 0; mi < 4; mi++)
            ldmatrix_x4(af[buf][mi][0], af[buf][mi][1], af[buf][mi][2], af[buf][mi][3],
                        dA + (aB[mi] ^ kx));
#pragma unroll
        for (int nb = 0; nb < 4; nb++)
            ldmatrix_x4(bf[buf][2 * nb][0], bf[buf][2 * nb][1],
                        bf[buf][2 * nb + 1][0], bf[buf][2 * nb + 1][1],
                        dB + (bB4[nb] ^ kx));
    };

    for (int c = 0; c < NCHUNK; c++) {
        int s = c % STAGES;
        asm volatile("cp.async.wait_group 1;" ::: "memory");
        __syncthreads();   // chunk c visible everywhere; stage (c-1)%3 reads all done
        if (c + 2 < NCHUNK) load_chunk(c + 2, (c + 2) % STAGES);
        else asm volatile("cp.async.commit_group;" ::: "memory");

        uint32_t dA = sb + s * STAGE_BYTES;
        uint32_t dB = dA + STAGE_A;

        // prime k-step 0 fragments
        prime(0, dA, dB, 0);

#pragma unroll
        for (int ks = 0; ks < 4; ks++) {
            int cur = ks & 1, nxt = cur ^ 1;
            if (ks < 3)   // prefetch next k-step under current HMMAs
                prime(nxt, dA, dB, (uint32_t)((ks + 1) << 5));
#pragma unroll
            for (int mi = 0; mi < 4; mi++)
#pragma unroll
                for (int ni = 0; ni < 8; ni++)
                    mma16816h(acc[mi][ni], af[cur][mi], bf[cur][ni]);
        }
    }

    // ---- epilogue: exp(2*sim), row sums (and col sums via symmetry) ----
    int rBase = tm * 128 + rWarp;
    int cBase = tn * 128 + cWarp;
    int sc = ((tm < (NTILE / 2)) == (tn < (NTILE / 2))) ? 0 : 1;

    float rsum[4][2];
    float csum[8][2];
#pragma unroll
    for (int i = 0; i < 4; i++) { rsum[i][0] = rsum[i][1] = 0.f; }
#pragma unroll
    for (int i = 0; i < 8; i++) { csum[i][0] = csum[i][1] = 0.f; }

#pragma unroll
    for (int mi = 0; mi < 4; mi++) {
        int grow0 = rBase + mi * 16 + (lane >> 2);
        int grow1 = grow0 + 8;
#pragma unroll
        for (int ni = 0; ni < 8; ni++) {
            int gc = cBase + ni * 8 + 2 * (lane & 3);
            float2 lo = __half22float2(*(__half2*)&acc[mi][ni][0]);  // (grow0,gc) (grow0,gc+1)
            float2 hi = __half22float2(*(__half2*)&acc[mi][ni][1]);  // (grow1,gc) (grow1,gc+1)
            float e0 = __expf(2.f * lo.x);
            float e1 = __expf(2.f * lo.y);
            float e2 = __expf(2.f * hi.x);
            float e3 = __expf(2.f * hi.y);
            if (diag) {
                if (grow0 == gc)     e0 = 0.f;
                if (grow0 == gc + 1) e1 = 0.f;
                if (grow1 == gc)     e2 = 0.f;
                if (grow1 == gc + 1) e3 = 0.f;
            }
            rsum[mi][0] += e0 + e1;
            rsum[mi][1] += e2 + e3;
            csum[ni][0] += e0 + e2;
            csum[ni][1] += e1 + e3;
        }
    }

    // row sums: reduce across lanes sharing a row (lane&3 varies -> xor 1,2)
#pragma unroll
    for (int mi = 0; mi < 4; mi++) {
#pragma unroll
        for (int j = 0; j < 2; j++) {
            float v = rsum[mi][j];
            v += __shfl_xor_sync(0xffffffffu, v, 1);
            v += __shfl_xor_sync(0xffffffffu, v, 2);
            if ((lane & 3) == 0) {
                int grow = rBase + mi * 16 + (lane >> 2) + j * 8;
                atomicAdd(&g_S[sc][f][grow], v);
            }
        }
    }

    // col sums (symmetric contribution) only for off-diagonal tiles:
    if (!diag) {
#pragma unroll
        for (int ni = 0; ni < 8; ni++) {
#pragma unroll
            for (int j = 0; j < 2; j++) {
                float v = csum[ni][j];
                v += __shfl_xor_sync(0xffffffffu, v, 4);
                v += __shfl_xor_sync(0xffffffffu, v, 8);
                v += __shfl_xor_sync(0xffffffffu, v, 16);
                if (lane < 4) {
                    int gc = cBase + ni * 8 + 2 * lane + j;
                    atomicAdd(&g_S[sc][f][gc], v);
                }
            }
        }
    }
}

// ---------------- kernel 4: final loss reduction (1024 thr, 16 independent elems each) ----
__global__ void loss_kernel(float* __restrict__ out) {
    __shared__ float ws[32];
    int t = threadIdx.x;
    float nom[16], cr[16];
#pragma unroll
    for (int i = 0; i < 16; i++) {
        int idx = t + i * 1024;
        int f = idx >> 13, r = idx & (BATCH - 1);
        nom[i] = g_S[0][f][r];
        cr[i]  = g_S[1][f][r];
    }
    float p = 0.f;
#pragma unroll
    for (int i = 0; i < 16; i++)
        p += -logf(nom[i] / (nom[i] + cr[i]) + 1e-8f);
#pragma unroll
    for (int o = 16; o; o >>= 1) p += __shfl_xor_sync(0xffffffffu, p, o);
    if ((t & 31) == 0) ws[t >> 5] = p;
    __syncthreads();
    if (t == 0) {
        float a = 0.f;
#pragma unroll
        for (int w = 0; w < 32; w++) a += ws[w];
        out[0] = a * (1.0f / HALF_B);
    }
}

// ---------------- launch ----------------
extern "C" void kernel_launch(void* const* d_in, const int* in_sizes, int n_in,
                              void* d_out, int out_size) {
    const float* text  = (const float*)d_in[0];
    const float* image = (const float*)d_in[1];
    const int*   label = (const int*)d_in[2];

    void* sAddr = nullptr;
    cudaGetSymbolAddress(&sAddr, g_S);
    cudaMemsetAsync(sAddr, 0, sizeof(float) * 2 * 2 * BATCH);   // launch idx 0

    perm_kernel<<<1, 1024>>>(label);                            // idx 1
    norm_kernel<<<dim3(BATCH, 2), 256>>>(text, image);          // idx 2
    dummy_kernel<<<1, 32>>>();                                  // idx 3

    cudaFuncSetAttribute(gram_kernel, cudaFuncAttributeMaxDynamicSharedMemorySize, SMEM_DYN);
    gram_kernel<<<dim3(NPAIR, 2), 128, SMEM_DYN>>>();           // idx 4  (ncu window)

    loss_kernel<<<1, 1024>>>((float*)d_out);                    // idx 5
}

// round 13
// speedup vs baseline: 1.1150x; 1.1150x over previous
#include <cuda_runtime.h>
#include <cuda_fp16.h>
#include <cstdint>

#define BATCH   8192
#define DIM     1024
#define HALF_B  4096

// ---------------- device scratch (static, no runtime alloc) ----------------
__device__ __half g_P[2][BATCH][DIM];          // permuted, normalized, fp16 (32 MB)
__device__ int   g_perm[BATCH];
__device__ float g_S[2][2][BATCH];             // [same=0/cross=1][feature][row]

// ---------------- helpers ----------------
__device__ __forceinline__ uint32_t smem_u32(const void* p) {
    uint32_t a;
    asm("{ .reg .u64 t; cvta.to.shared.u64 t, %1; cvt.u32.u64 %0, t; }" : "=r"(a) : "l"(p));
    return a;
}
__device__ __forceinline__ void cpa16(uint32_t s, const void* g) {
    asm volatile("cp.async.cg.shared.global [%0], [%1], 16;" :: "r"(s), "l"(g) : "memory");
}
#define SWZ(o) ((o) ^ (((o) >> 3) & 0x70))

__device__ __forceinline__ void ldmatrix_x4(uint32_t& r0, uint32_t& r1, uint32_t& r2, uint32_t& r3,
                                            uint32_t addr) {
    asm volatile("ldmatrix.sync.aligned.m8n8.x4.shared.b16 {%0,%1,%2,%3}, [%4];"
                 : "=r"(r0), "=r"(r1), "=r"(r2), "=r"(r3) : "r"(addr));
}
// fp16 MMA with fp16 accumulators: D(2 regs) = A(4) * B(2) + D
__device__ __forceinline__ void mma16816h(uint32_t* c, const uint32_t* a, const uint32_t* b) {
    asm volatile("mma.sync.aligned.m16n8k16.row.col.f16.f16.f16.f16 "
                 "{%0,%1}, {%2,%3,%4,%5}, {%6,%7}, {%0,%1};"
                 : "+r"(c[0]), "+r"(c[1])
                 : "r"(a[0]), "r"(a[1]), "r"(a[2]), "r"(a[3]), "r"(b[0]), "r"(b[1]));
}

// ---------------- kernel 1: permutation (stable partition by label) ----------------
__global__ void perm_kernel(const int* __restrict__ label) {
    __shared__ int wsum[32];
    int t = threadIdx.x;
    int l[8]; int c = 0;
#pragma unroll
    for (int i = 0; i < 8; i++) { l[i] = label[t * 8 + i]; c += l[i]; }
    int v = c, lane = t & 31, w = t >> 5;
#pragma unroll
    for (int o = 1; o < 32; o <<= 1) {
        int n = __shfl_up_sync(0xffffffffu, v, o);
        if (lane >= o) v += n;
    }
    if (lane == 31) wsum[w] = v;
    __syncthreads();
    if (w == 0) {
        int x = wsum[lane];
#pragma unroll
        for (int o = 1; o < 32; o <<= 1) {
            int n = __shfl_up_sync(0xffffffffu, x, o);
            if (lane >= o) x += n;
        }
        wsum[lane] = x;
    }
    __syncthreads();
    int run = v - c + (w ? wsum[w - 1] : 0);   // ones strictly before t*8
#pragma unroll
    for (int i = 0; i < 8; i++) {
        int idx = t * 8 + i;
        g_perm[idx] = l[i] ? run : (HALF_B + (idx - run));
        run += l[i];
    }
}

// ---------------- kernel 2: normalize + scatter to fp16 ----------------
__global__ void norm_kernel(const float* __restrict__ text, const float* __restrict__ image) {
    int f = blockIdx.y;
    int row = blockIdx.x;
    int t = threadIdx.x;
    const float4* src = (const float4*)((f == 0 ? text : image) + (size_t)row * DIM);
    float4 v = src[t];
    float s = v.x * v.x + v.y * v.y + v.z * v.z + v.w * v.w;
#pragma unroll
    for (int o = 16; o; o >>= 1) s += __shfl_xor_sync(0xffffffffu, s, o);
    __shared__ float ws[8];
    __shared__ float s_inv;
    if ((t & 31) == 0) ws[t >> 5] = s;
    __syncthreads();
    if (t == 0) {
        float a = 0.f;
#pragma unroll
        for (int wq = 0; wq < 8; wq++) a += ws[wq];
        s_inv = 1.0f / fmaxf(sqrtf(a), 1e-12f);
    }
    __syncthreads();
    float inv = s_inv;
    int dest = g_perm[row];
    __half* dst = &g_P[f][dest][0];
    __half2 a0 = __floats2half2_rn(v.x * inv, v.y * inv);
    __half2 a1 = __floats2half2_rn(v.z * inv, v.w * inv);
    ((__half2*)dst)[2 * t]     = a0;
    ((__half2*)dst)[2 * t + 1] = a1;
}

// ---------------- dummy kernel (aligns ncu capture window onto gram_kernel) --------
__global__ void dummy_kernel() {}

// ---------------- kernel 3: symmetric Gram GEMM (HMMA f16-accum) + exp-sum epilogue
// 128x128 tile per CTA, lower-triangular tile pairs only. 4 warps, warp tile 64x64.
// 3 CTAs/SM (2-stage 64KB smem pipeline, <=170 regs via f16 accumulators):
// 3 warps/SMSP cover chunk-boundary latency with warp parallelism.
constexpr int NCHUNK = DIM / 64, STAGES = 2;
constexpr int STAGE_A = 128 * 128;          // 16 KB (128 rows x 64 fp16)
constexpr int STAGE_BYTES = 2 * STAGE_A;    // 32 KB (A + B)
constexpr int SMEM_DYN = STAGES * STAGE_BYTES;   // 64 KB
constexpr int NTILE = BATCH / 128;          // 64
constexpr int NPAIR = NTILE * (NTILE + 1) / 2;   // 2080

__global__ void __launch_bounds__(128, 3) gram_kernel() {
    extern __shared__ __align__(1024) char smem_raw[];
    uint32_t sb = smem_u32(smem_raw);
    int tid = threadIdx.x, lane = tid & 31, wid = tid >> 5;
    int p = blockIdx.x, f = blockIdx.y;

    // triangular decode: tm >= tn
    int tm = (int)((sqrtf(8.f * (float)p + 1.f) - 1.f) * 0.5f);
    while ((tm + 1) * (tm + 2) / 2 <= p) tm++;
    while (tm * (tm + 1) / 2 > p) tm--;
    int tn = p - tm * (tm + 1) / 2;
    bool diag = (tm == tn);

    const char* baseA = (const char*)&g_P[f][tm * 128][0];
    const char* baseB = (const char*)&g_P[f][tn * 128][0];

    auto load_chunk = [&](int c, int s) {
        uint32_t dA = sb + s * STAGE_BYTES;
        uint32_t dB = dA + STAGE_A;
        const char* gA = baseA + c * 128;
        const char* gB = baseB + c * 128;
#pragma unroll
        for (int i = 0; i < 8; i++) {       // A: 128 rows x 8 segs = 1024 cp / 128 thr
            int o = tid + (i << 7); int r = o >> 3, sg = o & 7;
            cpa16(dA + SWZ(r * 128 + sg * 16), gA + (size_t)r * 2048 + sg * 16);
        }
#pragma unroll
        for (int i = 0; i < 8; i++) {
            int o = tid + (i << 7); int r = o >> 3, sg = o & 7;
            cpa16(dB + SWZ(r * 128 + sg * 16), gB + (size_t)r * 2048 + sg * 16);
        }
        asm volatile("cp.async.commit_group;" ::: "memory");
    };

    // prologue: both stages in flight
    load_chunk(0, 0);
    load_chunk(1, 1);

    int wm = wid & 1, wn = wid >> 1;
    int rWarp = wm * 64;            // warp's M offset within tile
    int cWarp = wn * 64;            // warp's N offset within tile
    int quad = lane >> 3, laneRow = lane & 7;
    int aRowOff = rWarp + (quad & 1) * 8 + laneRow;   // + mi*16
    int aColOff = (quad >> 1) * 8;                    // + ks*16 cols
    // B via x4: two n8-fragments (rows nb*16..nb*16+15) per op
    int bRow4 = cWarp + ((lane >> 4) & 1) * 8 + laneRow;  // + nb*16
    int bCol4 = ((lane >> 3) & 1) * 8;                    // k half

    // swizzled fragment base offsets (ks=0); addr(ks) = base ^ (32*ks)
    uint32_t aB[4], bB4[4];
#pragma unroll
    for (int mi = 0; mi < 4; mi++)
        aB[mi] = SWZ((uint32_t)((aRowOff + mi * 16) * 128 + aColOff * 2));
#pragma unroll
    for (int nb = 0; nb < 4; nb++)
        bB4[nb] = SWZ((uint32_t)((bRow4 + nb * 16) * 128 + bCol4 * 2));

    // fp16 accumulators: 2 regs per (mi,ni) fragment (half2 x2)
    uint32_t acc[4][8][2];
#pragma unroll
    for (int mi = 0; mi < 4; mi++)
#pragma unroll
        for (int ni = 0; ni < 8; ni++)
            acc[mi][ni][0] = acc[mi][ni][1] = 0u;

    uint32_t af[2][4][4], bf[2][8][2];

    auto prime = [&](int buf, uint32_t dA, uint32_t dB, uint32_t kx) {
#pragma unroll
        for (int mi = 0; mi < 4; mi++)
            ldmatrix_x4(af[buf][mi][0], af[buf][mi][1], af[buf][mi][2], af[buf][mi][3],
                        dA + (aB[mi] ^ kx));
#pragma unroll
        for (int nb = 0; nb < 4; nb++)
            ldmatrix_x4(bf[buf][2 * nb][0], bf[buf][2 * nb][1],
                        bf[buf][2 * nb + 1][0], bf[buf][2 * nb + 1][1],
                        dB + (bB4[nb] ^ kx));
    };

    for (int c = 0; c < NCHUNK; c++) {
        int s = c & 1;
        asm volatile("cp.async.wait_group 1;" ::: "memory");
        __syncthreads();   // chunk c visible to all warps

        uint32_t dA = sb + s * STAGE_BYTES;
        uint32_t dB = dA + STAGE_A;

        // prime k-step 0 fragments
        prime(0, dA, dB, 0);

#pragma unroll
        for (int ks = 0; ks < 4; ks++) {
            int cur = ks & 1, nxt = cur ^ 1;
            if (ks < 3)   // prefetch next k-step under current HMMAs
                prime(nxt, dA, dB, (uint32_t)((ks + 1) << 5));
#pragma unroll
            for (int mi = 0; mi < 4; mi++)
#pragma unroll
                for (int ni = 0; ni < 8; ni++)
                    mma16816h(acc[mi][ni], af[cur][mi], bf[cur][ni]);
        }

        // all LDSM reads of stage s are complete (last prime was ks3);
        // barrier, then refill stage s with chunk c+2
        __syncthreads();
        if (c + 2 < NCHUNK) load_chunk(c + 2, s);
        else asm volatile("cp.async.commit_group;" ::: "memory");  // keep accounting
    }

    // ---- epilogue: exp(2*sim), row sums (and col sums via symmetry) ----
    int rBase = tm * 128 + rWarp;
    int cBase = tn * 128 + cWarp;
    int sc = ((tm < (NTILE / 2)) == (tn < (NTILE / 2))) ? 0 : 1;

    float rsum[4][2];
    float csum[8][2];
#pragma unroll
    for (int i = 0; i < 4; i++) { rsum[i][0] = rsum[i][1] = 0.f; }
#pragma unroll
    for (int i = 0; i < 8; i++) { csum[i][0] = csum[i][1] = 0.f; }

#pragma unroll
    for (int mi = 0; mi < 4; mi++) {
        int grow0 = rBase + mi * 16 + (lane >> 2);
        int grow1 = grow0 + 8;
#pragma unroll
        for (int ni = 0; ni < 8; ni++) {
            int gc = cBase + ni * 8 + 2 * (lane & 3);
            float2 lo = __half22float2(*(__half2*)&acc[mi][ni][0]);  // (grow0,gc) (grow0,gc+1)
            float2 hi = __half22float2(*(__half2*)&acc[mi][ni][1]);  // (grow1,gc) (grow1,gc+1)
            float e0 = __expf(2.f * lo.x);
            float e1 = __expf(2.f * lo.y);
            float e2 = __expf(2.f * hi.x);
            float e3 = __expf(2.f * hi.y);
            if (diag) {
                if (grow0 == gc)     e0 = 0.f;
                if (grow0 == gc + 1) e1 = 0.f;
                if (grow1 == gc)     e2 = 0.f;
                if (grow1 == gc + 1) e3 = 0.f;
            }
            rsum[mi][0] += e0 + e1;
            rsum[mi][1] += e2 + e3;
            csum[ni][0] += e0 + e2;
            csum[ni][1] += e1 + e3;
        }
    }

    // row sums: reduce across lanes sharing a row (lane&3 varies -> xor 1,2)
#pragma unroll
    for (int mi = 0; mi < 4; mi++) {
#pragma unroll
        for (int j = 0; j < 2; j++) {
            float v = rsum[mi][j];
            v += __shfl_xor_sync(0xffffffffu, v, 1);
            v += __shfl_xor_sync(0xffffffffu, v, 2);
            if ((lane & 3) == 0) {
                int grow = rBase + mi * 16 + (lane >> 2) + j * 8;
                atomicAdd(&g_S[sc][f][grow], v);
            }
        }
    }

    // col sums (symmetric contribution) only for off-diagonal tiles:
    if (!diag) {
#pragma unroll
        for (int ni = 0; ni < 8; ni++) {
#pragma unroll
            for (int j = 0; j < 2; j++) {
                float v = csum[ni][j];
                v += __shfl_xor_sync(0xffffffffu, v, 4);
                v += __shfl_xor_sync(0xffffffffu, v, 8);
                v += __shfl_xor_sync(0xffffffffu, v, 16);
                if (lane < 4) {
                    int gc = cBase + ni * 8 + 2 * lane + j;
                    atomicAdd(&g_S[sc][f][gc], v);
                }
            }
        }
    }
}

// ---------------- kernel 4: final loss reduction (1024 thr, 16 independent elems each) ----
__global__ void loss_kernel(float* __restrict__ out) {
    __shared__ float ws[32];
    int t = threadIdx.x;
    float nom[16], cr[16];
#pragma unroll
    for (int i = 0; i < 16; i++) {
        int idx = t + i * 1024;
        int f = idx >> 13, r = idx & (BATCH - 1);
        nom[i] = g_S[0][f][r];
        cr[i]  = g_S[1][f][r];
    }
    float p = 0.f;
#pragma unroll
    for (int i = 0; i < 16; i++)
        p += -logf(nom[i] / (nom[i] + cr[i]) + 1e-8f);
#pragma unroll
    for (int o = 16; o; o >>= 1) p += __shfl_xor_sync(0xffffffffu, p, o);
    if ((t & 31) == 0) ws[t >> 5] = p;
    __syncthreads();
    if (t == 0) {
        float a = 0.f;
#pragma unroll
        for (int w = 0; w < 32; w++) a += ws[w];
        out[0] = a * (1.0f / HALF_B);
    }
}

// ---------------- launch ----------------
extern "C" void kernel_launch(void* const* d_in, const int* in_sizes, int n_in,
                              void* d_out, int out_size) {
    const float* text  = (const float*)d_in[0];
    const float* image = (const float*)d_in[1];
    const int*   label = (const int*)d_in[2];

    void* sAddr = nullptr;
    cudaGetSymbolAddress(&sAddr, g_S);
    cudaMemsetAsync(sAddr, 0, sizeof(float) * 2 * 2 * BATCH);   // launch idx 0

    perm_kernel<<<1, 1024>>>(label);                            // idx 1
    norm_kernel<<<dim3(BATCH, 2), 256>>>(text, image);          // idx 2
    dummy_kernel<<<1, 32>>>();                                  // idx 3

    cudaFuncSetAttribute(gram_kernel, cudaFuncAttributeMaxDynamicSharedMemorySize, SMEM_DYN);
    gram_kernel<<<dim3(NPAIR, 2), 128, SMEM_DYN>>>();           // idx 4  (ncu window)

    loss_kernel<<<1, 1024>>>((float*)d_out);                    // idx 5
}